// round 11
// baseline (speedup 1.0000x reference)
#include <cuda_runtime.h>
#include <cuda_bf16.h>
#include <cstdint>

#define S_LEN 512
#define BATCH 2048
#define DIN 64
#define HID 128
#define NROWS (S_LEN * BATCH)

// U scratch (split-packed bf16 pairs), lane-contiguous fragment-major layout:
// u32 index = bi*2048 + warp*256 + lane*8 + (r*2+nt)*2 + e
__device__ uint32_t g_U[(size_t)NROWS * HID];

__device__ __forceinline__ float fast_tanh(float v) {
    float e = __expf(2.0f * v);
    return 1.0f - __fdividef(2.0f, e + 1.0f);
}
__device__ __forceinline__ void ldsm4(uint32_t r[4], uint32_t addr) {
    asm volatile("ldmatrix.sync.aligned.m8n8.x4.shared.b16 {%0,%1,%2,%3}, [%4];"
                 : "=r"(r[0]), "=r"(r[1]), "=r"(r[2]), "=r"(r[3]) : "r"(addr));
}
__device__ __forceinline__ void mma_bf16(float d[4], const uint32_t a[4],
                                         const uint32_t b0, const uint32_t b1) {
    asm volatile("mma.sync.aligned.m16n8k16.row.col.f32.bf16.bf16.f32 "
                 "{%0,%1,%2,%3}, {%4,%5,%6,%7}, {%8,%9}, {%0,%1,%2,%3};"
                 : "+f"(d[0]), "+f"(d[1]), "+f"(d[2]), "+f"(d[3])
                 : "r"(a[0]), "r"(a[1]), "r"(a[2]), "r"(a[3]), "r"(b0), "r"(b1));
}
__device__ __forceinline__ uint32_t smem_u32(const void* p) {
    uint32_t a;
    asm("{ .reg .u64 t; cvta.to.shared.u64 t, %1; cvt.u32.u64 %0, t; }"
        : "=r"(a) : "l"(p));
    return a;
}
__device__ __forceinline__ uint32_t cvt2bf(float lo, float hi) {
    uint32_t r;
    asm("cvt.rn.bf16x2.f32 %0, %1, %2;" : "=r"(r) : "f"(hi), "f"(lo));
    return r;
}
// value of packed split element: low16 = main bf16, high16 = residual bf16
__device__ __forceinline__ float su(uint32_t p) {
    return __uint_as_float(p << 16) + __uint_as_float(p & 0xFFFF0000u);
}
__device__ __forceinline__ void split_pair(float v0, float v1,
                                           uint32_t& hi, uint32_t& lo) {
    hi = cvt2bf(v0, v1);
    float f0 = __uint_as_float(hi << 16);
    float f1 = __uint_as_float(hi & 0xFFFF0000u);
    lo = cvt2bf(v0 - f0, v1 - f1);
}

// ============ Kernel 1: U = x @ W_ih^T + b_ih via bf16 mma ================

#define P2_THREADS 256
#define P2_GRID 592
#define NTILES (NROWS / 32)
#define PROW 144
#define PWSPL (HID * PROW)
#define PXSPL (32 * PROW)
#define PXBUF (2 * PXSPL)
#define PW 0
#define PX (2 * PWSPL)
#define P2_SMEM (PX + 2 * PXBUF)

__global__ void __launch_bounds__(P2_THREADS)
precompute_kernel(const float* __restrict__ x, const float* __restrict__ Wih,
                  const float* __restrict__ bih)
{
    extern __shared__ unsigned char sm[];
    const uint32_t smem_b = smem_u32(sm);

    const int tid  = threadIdx.x;
    const int warp = tid >> 5;
    const int lane = tid & 31;
    const int tq   = lane & 3;
    const int rg   = warp >> 2;
    const int colWp = (warp & 3) * 32;

    // ---- stage W_ih splits (once) ----
    for (int idx = tid; idx < HID * DIN; idx += P2_THREADS) {
        const int n = idx >> 6, k = idx & 63;
        float w = Wih[idx];
        __nv_bfloat16 w0 = __float2bfloat16(w);
        __nv_bfloat16 w1 = __float2bfloat16(w - __bfloat162float(w0));
        const size_t off = (size_t)n * PROW + (size_t)k * 2;
        *(__nv_bfloat16*)(sm + PW + off)         = w0;
        *(__nv_bfloat16*)(sm + PW + PWSPL + off) = w1;
    }

    float bi0[4], bi1[4];
    #pragma unroll
    for (int nt = 0; nt < 4; ++nt) {
        bi0[nt] = bih[colWp + nt * 8 + tq * 2];
        bi1[nt] = bih[colWp + nt * 8 + tq * 2 + 1];
    }

    const int q  = lane >> 3;
    const int lr = lane & 7;
    const uint32_t xa_lane = (uint32_t)((rg * 16 + lr + (q & 1) * 8) * PROW +
                                        ((q & 2) ? 8 : 0) * 2);
    const uint32_t wb = smem_b + PW +
        (uint32_t)((colWp + lr + ((q & 2) ? 8 : 0)) * PROW + ((q & 1) ? 8 : 0) * 2);

    const int sr = tid >> 3;
    const int sc = (tid & 7) * 8;

    // ---- prologue: 2-deep tile prefetch ----
    int blk = blockIdx.x;
    float4 v0, v1, w0, w1;
    {
        const float* p = x + ((size_t)blk * 32 + sr) * DIN + sc;
        v0 = *(const float4*)p; v1 = *(const float4*)(p + 4);
        if (blk + P2_GRID < NTILES) {
            const float* pn = x + ((size_t)(blk + P2_GRID) * 32 + sr) * DIN + sc;
            w0 = *(const float4*)pn; w1 = *(const float4*)(pn + 4);
        }
    }
    int cur = 0;
    __syncthreads();

    while (blk < NTILES) {
        // ---- stage x tile splits: 2x STS.128 per thread ----
        {
            uint4 hi, lo;
            split_pair(v0.x, v0.y, hi.x, lo.x);
            split_pair(v0.z, v0.w, hi.y, lo.y);
            split_pair(v1.x, v1.y, hi.z, lo.z);
            split_pair(v1.z, v1.w, hi.w, lo.w);
            unsigned char* xb = sm + PX + cur * PXBUF + sr * PROW + sc * 2;
            *(uint4*)xb           = hi;
            *(uint4*)(xb + PXSPL) = lo;
        }
        __syncthreads();

        // ---- shift prefetch pipeline ----
        v0 = w0; v1 = w1;
        if (blk + 2 * P2_GRID < NTILES) {
            const float* p = x + ((size_t)(blk + 2 * P2_GRID) * 32 + sr) * DIN + sc;
            w0 = *(const float4*)p; w1 = *(const float4*)(p + 4);
        }

        // ---- mma: 2-way splits, 3 products ----
        float D[4][4], Dc[4][4];
        #pragma unroll
        for (int nt = 0; nt < 4; ++nt) {
            D[nt][0] = bi0[nt]; D[nt][1] = bi1[nt];
            D[nt][2] = bi0[nt]; D[nt][3] = bi1[nt];
            Dc[nt][0] = Dc[nt][1] = Dc[nt][2] = Dc[nt][3] = 0.0f;
        }
        const uint32_t xa = smem_b + PX + (uint32_t)cur * PXBUF + xa_lane;
        #pragma unroll
        for (int ks = 0; ks < 4; ++ks) {
            uint32_t A0[4], A1[4];
            ldsm4(A0, xa + ks * 32);
            ldsm4(A1, xa + PXSPL + ks * 32);
            #pragma unroll
            for (int np = 0; np < 2; ++np) {
                uint32_t B0[4], B1[4];
                ldsm4(B0, wb + (uint32_t)(np * 16 * PROW) + ks * 32);
                ldsm4(B1, wb + PWSPL + (uint32_t)(np * 16 * PROW) + ks * 32);
                #pragma unroll
                for (int hf = 0; hf < 2; ++hf) {
                    const int nt = np * 2 + hf;
                    mma_bf16(D[nt],  A0, B0[2 * hf], B0[2 * hf + 1]);
                    mma_bf16(Dc[nt], A0, B1[2 * hf], B1[2 * hf + 1]);
                    mma_bf16(Dc[nt], A1, B0[2 * hf], B0[2 * hf + 1]);
                }
            }
        }

        // ---- write U: lane-contiguous, 4x STG.128 per lane ----
        const size_t biBlk = ((size_t)blk * 32 >> 4) + rg;
        #pragma unroll
        for (int lwh = 0; lwh < 2; ++lwh) {          // loop-warp half: nt pair
            const int lw = 2 * (warp & 3) + lwh;
            #pragma unroll
            for (int r = 0; r < 2; ++r) {
                uint4 o;
                #pragma unroll
                for (int ntl = 0; ntl < 2; ++ntl) {
                    const int nt = lwh * 2 + ntl;
                    float s0 = D[nt][2 * r]     + Dc[nt][2 * r];
                    float s1 = D[nt][2 * r + 1] + Dc[nt][2 * r + 1];
                    uint32_t p, pr;
                    split_pair(s0, s1, p, pr);
                    if (ntl == 0) {
                        o.x = __byte_perm(p, pr, 0x5410);
                        o.y = __byte_perm(p, pr, 0x7632);
                    } else {
                        o.z = __byte_perm(p, pr, 0x5410);
                        o.w = __byte_perm(p, pr, 0x7632);
                    }
                }
                *(uint4*)&g_U[biBlk * 2048 + lw * 256 + lane * 8 + r * 4] = o;
            }
        }

        blk += P2_GRID;
        cur ^= 1;
    }
}

// ============ Kernel 2: recurrence, 12 mma chains, hoisted U unpack ========

#define ROWB 272
#define WSPL (HID * ROWB)
#define ASPL (16 * ROWB)
#define ABUF (2 * ASPL)
#define SM_W 0
#define SM_A (2 * WSPL)
#define L_SMEM (SM_A + 2 * ABUF)
#define L_THREADS 256

__global__ void __launch_bounds__(L_THREADS, 1)
loop_kernel(const float* __restrict__ h0, const float* __restrict__ bhh,
            const float* __restrict__ Whh, float* __restrict__ out)
{
    extern __shared__ unsigned char smem[];
    const uint32_t smem_b = smem_u32(smem);

    const int tid  = threadIdx.x;
    const int warp = tid >> 5;
    const int lane = tid & 31;
    const int g    = lane >> 2;
    const int tq   = lane & 3;
    const int bx   = blockIdx.x;
    const int rowBase = bx * 16;
    const int colW = warp * 16;

    for (int idx = tid; idx < HID * HID; idx += L_THREADS) {
        const int n = idx >> 7, k = idx & 127;
        float w = Whh[idx];
        __nv_bfloat16 w0 = __float2bfloat16(w);
        __nv_bfloat16 w1 = __float2bfloat16(w - __bfloat162float(w0));
        const size_t off = (size_t)n * ROWB + (size_t)k * 2;
        *(__nv_bfloat16*)(smem + SM_W + off)        = w0;
        *(__nv_bfloat16*)(smem + SM_W + WSPL + off) = w1;
    }

    float bh0[2], bh1[2];
    #pragma unroll
    for (int nt = 0; nt < 2; ++nt) {
        bh0[nt] = bhh[colW + nt * 8 + tq * 2];
        bh1[nt] = bhh[colW + nt * 8 + tq * 2 + 1];
    }

    // lane-contiguous U address (8 u32 per lane per bi)
    #define UADDR(bi) ((size_t)(bi) * 2048 + warp * 256 + lane * 8)

    // ---- h, a registers; stage a(0) splits ----
    float h[2][2][2], a[2][2][2];
    {
        uint4 u0 = *(const uint4*)&g_U[UADDR(bx)];      // r=0
        uint4 u1 = *(const uint4*)&g_U[UADDR(bx) + 4];  // r=1
        #pragma unroll
        for (int r = 0; r < 2; ++r) {
            const int row = rowBase + g + 8 * r;
            const uint4 uu = r ? u1 : u0;
            #pragma unroll
            for (int nt = 0; nt < 2; ++nt) {
                float2 hv = *(const float2*)&h0[(size_t)row * HID + colW + nt * 8 + tq * 2];
                h[r][nt][0] = hv.x; h[r][nt][1] = hv.y;
                const uint32_t ux = nt ? uu.z : uu.x;
                const uint32_t uy = nt ? uu.w : uu.y;
                a[r][nt][0] = su(ux) * hv.x;
                a[r][nt][1] = su(uy) * hv.y;
            }
        }
    }
    #pragma unroll
    for (int r = 0; r < 2; ++r) {
        const int lrow = g + 8 * r;
        #pragma unroll
        for (int nt = 0; nt < 2; ++nt) {
            uint32_t p, pr;
            split_pair(a[r][nt][0], a[r][nt][1], p, pr);
            const size_t o = (size_t)lrow * ROWB + (size_t)(colW + nt * 8 + tq * 2) * 2;
            *(uint32_t*)(smem + SM_A + o)        = p;
            *(uint32_t*)(smem + SM_A + ASPL + o) = pr;
        }
    }

    // ---- 2-deep U prefetch: Ua = U(1), Ub = U(2) ----
    uint4 Ua[2], Ub[2];
    Ua[0] = *(const uint4*)&g_U[UADDR(128 + bx)];
    Ua[1] = *(const uint4*)&g_U[UADDR(128 + bx) + 4];
    Ub[0] = *(const uint4*)&g_U[UADDR(256 + bx)];
    Ub[1] = *(const uint4*)&g_U[UADDR(256 + bx) + 4];
    __syncthreads();

    const int q  = lane >> 3;
    const int lr = lane & 7;
    const uint32_t a_off = (uint32_t)((lr + (q & 1) * 8) * ROWB + ((q & 2) ? 8 : 0) * 2);
    const uint32_t b_off = smem_b + SM_W +
        (uint32_t)((colW + lr + ((q & 2) ? 8 : 0)) * ROWB + ((q & 1) ? 8 : 0) * 2);

    // ---- preload W_hh B-fragments (loop-invariant) ----
    uint32_t Bf0[8][4], Bf1[8][4];
    #pragma unroll
    for (int ks = 0; ks < 8; ++ks) {
        ldsm4(Bf0[ks], b_off + ks * 32);
        ldsm4(Bf1[ks], b_off + WSPL + ks * 32);
    }

    const uint32_t abase = smem_b + SM_A;

    for (int t = 0; t < S_LEN; ++t) {
        const int buf = t & 1;

        // ---- hoisted U(t+1) unpack: independent work for mma-phase bubbles
        float Uf[2][2][2];
        #pragma unroll
        for (int r = 0; r < 2; ++r) {
            Uf[r][0][0] = su(Ua[r].x);
            Uf[r][0][1] = su(Ua[r].y);
            Uf[r][1][0] = su(Ua[r].z);
            Uf[r][1][1] = su(Ua[r].w);
        }

        // ---- mma: 3 products x 2 ks-parities = 12 chains of depth 4 ----
        float D0[2][2][4], D1[2][2][4], D2[2][2][4];
        #pragma unroll
        for (int nt = 0; nt < 2; ++nt) {
            D0[0][nt][0] = bh0[nt]; D0[0][nt][1] = bh1[nt];
            D0[0][nt][2] = bh0[nt]; D0[0][nt][3] = bh1[nt];
            #pragma unroll
            for (int e = 0; e < 4; ++e) {
                D0[1][nt][e] = 0.0f;
                D1[0][nt][e] = 0.0f; D1[1][nt][e] = 0.0f;
                D2[0][nt][e] = 0.0f; D2[1][nt][e] = 0.0f;
            }
        }

        const uint32_t abuf = abase + (uint32_t)buf * ABUF + a_off;
        #pragma unroll
        for (int ks = 0; ks < 8; ++ks) {
            const int par = ks & 1;
            uint32_t A0[4], A1[4];
            ldsm4(A0, abuf + ks * 32);
            ldsm4(A1, abuf + ASPL + ks * 32);
            #pragma unroll
            for (int nt = 0; nt < 2; ++nt) {
                mma_bf16(D0[par][nt], A0, Bf0[ks][2 * nt], Bf0[ks][2 * nt + 1]);
                mma_bf16(D1[par][nt], A0, Bf1[ks][2 * nt], Bf1[ks][2 * nt + 1]);
                mma_bf16(D2[par][nt], A1, Bf0[ks][2 * nt], Bf0[ks][2 * nt + 1]);
            }
        }

        // ---- epilogue ----
        #pragma unroll
        for (int r = 0; r < 2; ++r) {
            const int lrow = g + 8 * r;
            #pragma unroll
            for (int nt = 0; nt < 2; ++nt) {
                float P0 = (D0[0][nt][2 * r]     + D0[1][nt][2 * r]) +
                           (D1[0][nt][2 * r]     + D1[1][nt][2 * r]) +
                           (D2[0][nt][2 * r]     + D2[1][nt][2 * r]);
                float P1 = (D0[0][nt][2 * r + 1] + D0[1][nt][2 * r + 1]) +
                           (D1[0][nt][2 * r + 1] + D1[1][nt][2 * r + 1]) +
                           (D2[0][nt][2 * r + 1] + D2[1][nt][2 * r + 1]);
                float h0n = fast_tanh(fmaf(P0, h[r][nt][0], a[r][nt][0]));
                float h1n = fast_tanh(fmaf(P1, h[r][nt][1], a[r][nt][1]));
                h[r][nt][0] = h0n; h[r][nt][1] = h1n;
                float v0 = Uf[r][nt][0] * h0n;
                float v1 = Uf[r][nt][1] * h1n;
                a[r][nt][0] = v0; a[r][nt][1] = v1;

                uint32_t p, pr;
                split_pair(v0, v1, p, pr);
                const size_t o = (size_t)(buf ^ 1) * ABUF + (size_t)lrow * ROWB +
                                 (size_t)(colW + nt * 8 + tq * 2) * 2;
                *(uint32_t*)(smem + SM_A + o)        = p;
                *(uint32_t*)(smem + SM_A + ASPL + o) = pr;
            }
        }

        // ---- shift prefetch: Ua <- Ub, issue Ub = U(t+3) ----
        {
            const int tn = (t + 3 < S_LEN) ? t + 3 : S_LEN - 1;
            const size_t ub = UADDR(tn * 128 + bx);
            Ua[0] = Ub[0]; Ua[1] = Ub[1];
            Ub[0] = *(const uint4*)&g_U[ub];
            Ub[1] = *(const uint4*)&g_U[ub + 4];
        }
        __syncthreads();
    }

    #pragma unroll
    for (int r = 0; r < 2; ++r) {
        const int row = rowBase + g + 8 * r;
        #pragma unroll
        for (int nt = 0; nt < 2; ++nt)
            *(float2*)&out[(size_t)row * HID + colW + nt * 8 + tq * 2] =
                make_float2(h[r][nt][0], h[r][nt][1]);
    }
}

// ============================== launch =====================================

extern "C" void kernel_launch(void* const* d_in, const int* in_sizes, int n_in,
                              void* d_out, int out_size)
{
    const float* x   = (const float*)d_in[0];
    const float* h0  = (const float*)d_in[1];
    const float* Wih = (const float*)d_in[2];
    const float* bih = (const float*)d_in[3];
    const float* Whh = (const float*)d_in[4];
    const float* bhh = (const float*)d_in[5];

    cudaFuncSetAttribute(precompute_kernel,
                         cudaFuncAttributeMaxDynamicSharedMemorySize, P2_SMEM);
    precompute_kernel<<<P2_GRID, P2_THREADS, P2_SMEM>>>(x, Wih, bih);

    cudaFuncSetAttribute(loop_kernel,
                         cudaFuncAttributeMaxDynamicSharedMemorySize, L_SMEM);
    loop_kernel<<<BATCH / 16, L_THREADS, L_SMEM>>>(h0, bhh, Whh, (float*)d_out);
}